// round 8
// baseline (speedup 1.0000x reference)
#include <cuda_runtime.h>
#include <math.h>
#include <stdint.h>

#define T_STEPS 16
#define BATCH   64
#define DG      512
#define DH      1024
#define DOUT    512
#define S_STEPS 3
#define LAMBDA  0.95f
#define ETA     0.5f

#define NBLK 64
#define NTHR 512
#define KSPLIT_H 16
#define KSPLIT_O 8

// ---------------- device scratch ----------------
__device__ float g_h[BATCH * DH];
__device__ float g_parts[KSPLIT_H][BATCH * DH];
__device__ float g_zwg[T_STEPS * BATCH * DH];
__device__ float g_hist[T_STEPS - 1][BATCH * DH];
__device__ float g_gram[BATCH * 256];
__device__ float g_hsum[BATCH * 16];
__device__ float g_hp[KSPLIT_O][BATCH * DOUT];
__device__ float g_lossb[BATCH];
__device__ float g_accb[BATCH];

// pre-packed tf32 hi/lo B-fragments (frag-order) for the three weight matrices
__device__ float g_whf_hi[DH * DH];
__device__ float g_whf_lo[DH * DH];
__device__ float g_wgf_hi[DH * DG];
__device__ float g_wgf_lo[DH * DG];
__device__ float g_hwf_hi[DOUT * DH];
__device__ float g_hwf_lo[DOUT * DH];

// grid barrier
__device__ unsigned g_bar_cnt = 0;
__device__ volatile unsigned g_bar_gen = 0;

__device__ __forceinline__ void bar_sync(unsigned& gen) {
    __syncthreads();
    if (threadIdx.x == 0) {
        __threadfence();
        unsigned t = atomicAdd(&g_bar_cnt, 1u);
        if (t == NBLK - 1) {
            g_bar_cnt = 0u;
            __threadfence();
            g_bar_gen = gen + 1u;
        } else {
            while (g_bar_gen == gen) __nanosleep(32);
        }
    }
    __syncthreads();
    gen++;
}

// ---------------- tf32 helpers ----------------
__device__ __forceinline__ uint32_t f2tf32(float x) {
    uint32_t r;
    asm("cvt.rna.tf32.f32 %0, %1;" : "=r"(r) : "f"(x));
    return r;
}

__device__ __forceinline__ void mma8(float* c, uint4 a, uint32_t b0, uint32_t b1) {
    asm volatile(
        "mma.sync.aligned.m16n8k8.row.col.f32.tf32.tf32.f32 "
        "{%0,%1,%2,%3}, {%4,%5,%6,%7}, {%8,%9}, {%0,%1,%2,%3};"
        : "+f"(c[0]), "+f"(c[1]), "+f"(c[2]), "+f"(c[3])
        : "r"(a.x), "r"(a.y), "r"(a.z), "r"(a.w), "r"(b0), "r"(b1));
}

// ---------------- B-fragment prepack (one-time prolog) ----------------
// W row-major [N][K].  Frag addr for element (n,k):
//   n8=n>>3, k8=k>>3, lane=(n&7)*4+(k&3), reg=(k>>2)&1
//   addr = ((n8*(K/8) + k8)*32 + lane)*2 + reg
__device__ void pack_w(const float* __restrict__ W, float* __restrict__ hi,
                       float* __restrict__ lo, int NK, int klog, int kfrag8) {
    const int kmask = (1 << klog) - 1;
    for (int idx = blockIdx.x * NTHR + threadIdx.x; idx < NK; idx += NBLK * NTHR) {
        int n = idx >> klog, k = idx & kmask;
        float v = W[idx];
        uint32_t hb = f2tf32(v);
        uint32_t lb = f2tf32(v - __uint_as_float(hb));
        int n8 = n >> 3, k8 = k >> 3;
        int lane = (n & 7) * 4 + (k & 3);
        int reg = (k >> 2) & 1;
        size_t a = ((size_t)(n8 * kfrag8 + k8) * 32 + lane) * 2 + reg;
        hi[a] = __uint_as_float(hb);
        lo[a] = __uint_as_float(lb);
    }
}

// ---------------- A pack: X tile (64 rows x 64 k) -> smem frag order ----
// As layout: [k8 0..7][mtile 0..3][lane 0..31][reg 0..3]
__device__ __forceinline__ void a_pack(uint32_t* As_hi, uint32_t* As_lo,
                                       const float* __restrict__ X, int ldx, int k0) {
    const int t = threadIdx.x;
    const int row = t >> 3, cseg = t & 7;
    const float4* p = (const float4*)(X + (size_t)row * ldx + k0 + cseg * 8);
    float4 v0 = p[0], v1 = p[1];
    float xv[8] = {v0.x, v0.y, v0.z, v0.w, v1.x, v1.y, v1.z, v1.w};
    const int tr = row & 15, mt = row >> 4;
#pragma unroll
    for (int c = 0; c < 8; c++) {
        int reg = (tr >= 8 ? 1 : 0) + (c >= 4 ? 2 : 0);
        int lane = (tr & 7) * 4 + (c & 3);
        int idx = ((cseg * 4 + mt) * 32 + lane) * 4 + reg;
        uint32_t hb = f2tf32(xv[c]);
        uint32_t lb = f2tf32(xv[c] - __uint_as_float(hb));
        As_hi[idx] = hb;
        As_lo[idx] = lb;
    }
}

// ---------------- tf32x3 GEMM: out[m 0..63][n0..n0+255] over k --------
// 512 thr = 16 warps: warp (mw 0..3, nw 0..3) computes m16 x n64.
// X fp32 [64 x ldx]; W frags prepacked; out fp32 row-major ldo.
__device__ void gemm_tf32(uint32_t* As_hi, uint32_t* As_lo,
                          const float* __restrict__ X, int ldx,
                          const float* __restrict__ Whi,
                          const float* __restrict__ Wlo,
                          int kfrag8, int n0, int k0, int nch,
                          float* __restrict__ out, int ldo) {
    const int tid = threadIdx.x;
    const int warp = tid >> 5, lane = tid & 31;
    const int mw = warp >> 2, nw = warp & 3;

    float c[8][4];
#pragma unroll
    for (int i = 0; i < 8; i++)
#pragma unroll
        for (int j = 0; j < 4; j++) c[i][j] = 0.f;

    for (int ch = 0; ch < nch; ch++) {
        __syncthreads();
        a_pack(As_hi, As_lo, X, ldx, k0 + ch * 64);
        __syncthreads();
        const int k8base = (k0 + ch * 64) >> 3;
#pragma unroll 1
        for (int k8 = 0; k8 < 8; k8++) {
            const int ai = ((k8 * 4 + mw) * 32 + lane) * 4;
            uint4 ah = *(const uint4*)&As_hi[ai];
            uint4 al = *(const uint4*)&As_lo[ai];
            const int k8g = k8base + k8;
#pragma unroll
            for (int t8 = 0; t8 < 8; t8++) {
                const int n8g = (n0 + nw * 64 + t8 * 8) >> 3;
                const size_t ba = ((size_t)(n8g * kfrag8 + k8g) * 32 + lane) * 2;
                float2 bh = *(const float2*)&Whi[ba];
                float2 bl = *(const float2*)&Wlo[ba];
                uint32_t bh0 = __float_as_uint(bh.x), bh1 = __float_as_uint(bh.y);
                uint32_t bl0 = __float_as_uint(bl.x), bl1 = __float_as_uint(bl.y);
                mma8(c[t8], ah, bh0, bh1);   // hi*hi
                mma8(c[t8], ah, bl0, bl1);   // hi*lo
                mma8(c[t8], al, bh0, bh1);   // lo*hi
            }
        }
    }

    // epilogue: c0,c1 -> (row gid, cols 2tig,2tig+1); c2,c3 -> row gid+8
    const int gid = lane >> 2, tig = lane & 3;
#pragma unroll
    for (int t8 = 0; t8 < 8; t8++) {
        const int n = n0 + nw * 64 + t8 * 8 + tig * 2;
        const int m = mw * 16 + gid;
        *(float2*)&out[(size_t)m * ldo + n] = make_float2(c[t8][0], c[t8][1]);
        *(float2*)&out[(size_t)(m + 8) * ldo + n] = make_float2(c[t8][2], c[t8][3]);
    }
}

// ---------------- 512-thread multi-value block reduction ----------------
template <int NV>
__device__ __forceinline__ void reduce512(const float* v, float* bc, float (*red)[18]) {
    const int lane = threadIdx.x & 31, warp = threadIdx.x >> 5;
#pragma unroll
    for (int x = 0; x < NV; x++) {
        float s = v[x];
#pragma unroll
        for (int o = 16; o > 0; o >>= 1) s += __shfl_down_sync(0xffffffffu, s, o);
        if (lane == 0) red[warp][x] = s;
    }
    __syncthreads();
#pragma unroll
    for (int x = warp; x < NV; x += 16) {
        float s = (lane < 16) ? red[lane][x] : 0.f;
#pragma unroll
        for (int o = 8; o > 0; o >>= 1) s += __shfl_down_sync(0xffffffffu, s, o);
        if (lane == 0) bc[x] = s;
    }
    __syncthreads();
}

// ---------------- refine phase (block = batch element) ------------------
__device__ void refine_phase(int b, int t, bool last,
                             const float* __restrict__ b_h,
                             const float* __restrict__ gam,
                             const float* __restrict__ bet,
                             const float* __restrict__ alp) {
    const int tid = threadIdx.x, lane = tid & 31, warp = tid >> 5;
    const int i0 = tid, i1 = tid + 512;

    __shared__ float red[16][18];
    __shared__ float bcS[18];
    __shared__ float bc0[18];
    __shared__ float Gs[256];
    __shared__ float hsums[16];
    __shared__ float es[16];
    __shared__ float coef[4];

    const float g0 = gam[i0], g1 = gam[i1];
    const float be0 = bet[i0], be1 = bet[i1];

    float hb0 = b_h[i0] + __ldcg(&g_zwg[((size_t)t * BATCH + b) * DH + i0]);
    float hb1 = b_h[i1] + __ldcg(&g_zwg[((size_t)t * BATCH + b) * DH + i1]);
    if (t > 0) {
#pragma unroll
        for (int s = 0; s < KSPLIT_H; s++) {
            hb0 += __ldcg(&g_parts[s][b * DH + i0]);
            hb1 += __ldcg(&g_parts[s][b * DH + i1]);
        }
    }

    float hv0[15], hv1[15];
#pragma unroll
    for (int tau = 0; tau < 15; tau++) {
        hv0[tau] = g_hist[tau][b * DH + i0];
        hv1[tau] = g_hist[tau][b * DH + i1];
    }

    if (tid < 256) Gs[tid] = g_gram[b * 256 + tid];
    if (tid < 16)  hsums[tid] = g_hsum[b * 16 + tid];

    {
        float p[17];
#pragma unroll
        for (int tau = 0; tau < 15; tau++)
            p[tau] = hv0[tau] * hb0 + hv1[tau] * hb1;
        p[15] = hb0 + hb1;
        p[16] = hb0 * hb0 + hb1 * hb1;
        reduce512<17>(p, bc0, red);
    }

    float mu = bc0[15] * (1.f / DH);
    float var = bc0[16] * (1.f / DH) - mu * mu;
    float rstd = rsqrtf(var + 1e-5f);
    float h0 = fmaxf((hb0 - mu) * rstd * g0 + be0, 0.f);
    float h1 = fmaxf((hb1 - mu) * rstd * g1 + be1, 0.f);

    const float alpha = *alp;
    float wdl = 0.f;
    if (warp == 0 && lane < t)
        wdl = ETA * powf(LAMBDA, (float)(t - 1 - lane));

#pragma unroll
    for (int s = 0; s < S_STEPS; s++) {
        {
            float qv[16];
#pragma unroll
            for (int tau = 0; tau < 15; tau++)
                qv[tau] = hv0[tau] * h0 + hv1[tau] * h1;
            qv[15] = h0 * h0 + h1 * h1;
            reduce512<16>(qv, bcS, red);
        }

        if (warp == 0) {
            float d = (lane < 16) ? bcS[lane] : 0.f;
            float e = wdl * d;
            if (lane < 16) es[lane] = e;
            __syncwarp();
            float f = 0.f;
            if (lane < 16) {
#pragma unroll
                for (int sg = 0; sg < 15; sg++)
                    f += es[sg] * Gs[lane * 16 + sg];
            }
            float hbd = (lane < 16) ? bc0[lane] : 0.f;
            float hsm = (lane < 16) ? hsums[lane] : 0.f;
            float pA = e * d;
            float pB = e * hbd;
            float pC = e * hsm;
            float pD = e * f;
#pragma unroll
            for (int o = 8; o > 0; o >>= 1) {
                pA += __shfl_down_sync(0xffffffffu, pA, o);
                pB += __shfl_down_sync(0xffffffffu, pB, o);
                pC += __shfl_down_sync(0xffffffffu, pC, o);
                pD += __shfl_down_sync(0xffffffffu, pD, o);
            }
            if (lane == 0) {
                float c1, c2;
                if (!last) {
                    float hh = bcS[15];
                    float n1 = sqrtf(hh) + 1e-6f;
                    float n2 = sqrtf(fmaxf(pD, 0.f)) + 1e-6f;
                    float R  = pA / (n1 * n2 + 1e-6f);
                    float Rp = fminf(fmaxf(R, 0.f), 1.f);
                    float spp = fmaxf(alpha, 0.f) + log1pf(expf(-fabsf(alpha)));
                    float spn = fmaxf(-alpha, 0.f) + log1pf(expf(-fabsf(alpha)));
                    float kco = (alpha >= 0.f) ? (1.f + spp) : (1.f / (1.f + spn));
                    float a   = 1.f - powf(1.f - Rp, kco);
                    c1 = 1.f - a * a;
                    c2 = a;
                } else {
                    c1 = 1.f;
                    c2 = 1.f;
                }
                float sum_hn  = c1 * bc0[15] + c2 * pC;
                float sum_hn2 = c1 * c1 * bc0[16] + 2.f * c1 * c2 * pB +
                                c2 * c2 * pD;
                float mu_n  = sum_hn * (1.f / DH);
                float var_n = sum_hn2 * (1.f / DH) - mu_n * mu_n;
                coef[0] = c1;
                coef[1] = c2;
                coef[2] = mu_n;
                coef[3] = rsqrtf(var_n + 1e-5f);
            }
        }
        __syncthreads();

        float Ah0 = 0.f, Ah1 = 0.f;
#pragma unroll
        for (int tau = 0; tau < 15; tau++) {
            Ah0 += es[tau] * hv0[tau];
            Ah1 += es[tau] * hv1[tau];
        }
        const float c1 = coef[0], c2 = coef[1], mun = coef[2], rsn = coef[3];
        float hn0 = c1 * hb0 + c2 * Ah0;
        float hn1 = c1 * hb1 + c2 * Ah1;
        h0 = fmaxf((hn0 - mun) * rsn * g0 + be0, 0.f);
        h1 = fmaxf((hn1 - mun) * rsn * g1 + be1, 0.f);
        __syncthreads();
    }

    g_h[b * DH + i0] = h0;
    g_h[b * DH + i1] = h1;

    if (!last) {
        float r[17];
#pragma unroll
        for (int tau = 0; tau < 15; tau++)
            r[tau] = hv0[tau] * h0 + hv1[tau] * h1;
        r[15] = h0 + h1;
        r[16] = h0 * h0 + h1 * h1;
        reduce512<17>(r, bcS, red);
        if (tid < t) {
            g_gram[b * 256 + t * 16 + tid] = bcS[tid];
            g_gram[b * 256 + tid * 16 + t] = bcS[tid];
        }
        if (tid == 0) {
            g_gram[b * 256 + t * 16 + t] = bcS[16];
            g_hsum[b * 16 + t] = bcS[15];
        }
        g_hist[t][b * DH + i0] = h0;
        g_hist[t][b * DH + i1] = h1;
    }
}

// ---------------- loss phase ----------------
__device__ void loss_phase(int b, const float* __restrict__ clean,
                           const float* __restrict__ head_b) {
    const int o = threadIdx.x;
    __shared__ float red[16][18];
    __shared__ float bc[18];
    float pred = head_b[o];
#pragma unroll
    for (int s = 0; s < KSPLIT_O; s++) pred += __ldcg(&g_hp[s][b * DOUT + o]);
    float c = clean[b * DOUT + o];
    float d = pred - c;
    float v[4] = {pred * c, pred * pred, c * c, d * d};
    reduce512<4>(v, bc, red);
    if (o == 0) {
        g_lossb[b] = bc[3] / (bc[2] + 1e-6f);
        g_accb[b]  = bc[0] / ((sqrtf(bc[1]) + 1e-6f) * (sqrtf(bc[2]) + 1e-6f));
    }
}

// ---------------- the one persistent kernel ----------------
__global__ void __launch_bounds__(NTHR, 1) fused_kernel(
    const float* __restrict__ z_seq, const float* __restrict__ clean,
    const float* __restrict__ W_h, const float* __restrict__ W_g,
    const float* __restrict__ b_h, const float* __restrict__ ln_g,
    const float* __restrict__ ln_b, const float* __restrict__ alpha,
    const float* __restrict__ head_W, const float* __restrict__ head_b,
    float* __restrict__ out) {
    __shared__ __align__(16) uint32_t As_hi[8 * 4 * 32 * 4];   // 16 KB
    __shared__ __align__(16) uint32_t As_lo[8 * 4 * 32 * 4];   // 16 KB

    unsigned gen = g_bar_gen;
    const int bi = blockIdx.x;

    // phase 0: prepack all weight matrices into tf32 hi/lo fragments
    pack_w(W_g,    g_wgf_hi, g_wgf_lo, DH * DG,  9, DG / 8);
    pack_w(W_h,    g_whf_hi, g_whf_lo, DH * DH, 10, DH / 8);
    pack_w(head_W, g_hwf_hi, g_hwf_lo, DOUT * DH, 10, DH / 8);
    bar_sync(gen);

    // phase 1: zwg = z @ W_g^T  (1024 x 1024 x 512), 16 m-tiles x 4 n-tiles
    {
        const int mt = bi >> 2, nt = bi & 3;
        gemm_tf32(As_hi, As_lo,
                  z_seq + (size_t)mt * 64 * DG, DG,
                  g_wgf_hi, g_wgf_lo, DG / 8,
                  nt * 256, 0, 8,
                  g_zwg + (size_t)mt * 64 * DH, DH);
    }
    bar_sync(gen);

    for (int t = 0; t < T_STEPS; t++) {
        if (t > 0) {
            // wh: 4 n-tiles x 16 k-splits (k=64) = 64 blocks
            const int nt = bi & 3, ks = bi >> 2;
            gemm_tf32(As_hi, As_lo, g_h, DH,
                      g_whf_hi, g_whf_lo, DH / 8,
                      nt * 256, ks * 64, 1,
                      g_parts[ks], DH);
            bar_sync(gen);
        }
        refine_phase(bi, t, t == T_STEPS - 1, b_h, ln_g, ln_b, alpha);
        bar_sync(gen);
    }

    // head GEMM: 2 n-tiles x 8 k-splits (k=128) = 16 blocks
    if (bi < 16) {
        const int nt = bi & 1, ks = bi >> 1;
        gemm_tf32(As_hi, As_lo, g_h, DH,
                  g_hwf_hi, g_hwf_lo, DH / 8,
                  nt * 256, ks * 128, 2,
                  g_hp[ks], DOUT);
    }
    bar_sync(gen);

    loss_phase(bi, clean, head_b);
    bar_sync(gen);

    if (bi == 0 && threadIdx.x < 32) {
        const int lane = threadIdx.x;
        float l = g_lossb[lane] + g_lossb[lane + 32];
        float a = g_accb[lane] + g_accb[lane + 32];
#pragma unroll
        for (int o = 16; o > 0; o >>= 1) {
            l += __shfl_down_sync(0xffffffffu, l, o);
            a += __shfl_down_sync(0xffffffffu, a, o);
        }
        if (lane == 0) {
            out[0] = l * (1.f / BATCH);
            out[1] = a * (1.f / BATCH);
        }
    }
}

// ---------------- launch ----------------
extern "C" void kernel_launch(void* const* d_in, const int* in_sizes, int n_in,
                              void* d_out, int out_size) {
    const float* z_seq  = (const float*)d_in[0];
    const float* clean  = (const float*)d_in[1];
    const float* W_h    = (const float*)d_in[2];
    const float* W_g    = (const float*)d_in[3];
    const float* b_h    = (const float*)d_in[4];
    const float* ln_g   = (const float*)d_in[5];
    const float* ln_b   = (const float*)d_in[6];
    const float* alpha  = (const float*)d_in[7];
    const float* head_W = (const float*)d_in[8];
    const float* head_b = (const float*)d_in[9];
    float* out = (float*)d_out;

    fused_kernel<<<NBLK, NTHR>>>(z_seq, clean, W_h, W_g, b_h, ln_g, ln_b,
                                 alpha, head_W, head_b, out);
}

// round 9
// speedup vs baseline: 1.0044x; 1.0044x over previous
#include <cuda_runtime.h>
#include <math.h>
#include <stdint.h>

#define T_STEPS 16
#define BATCH   64
#define DG      512
#define DH      1024
#define DOUT    512
#define S_STEPS 3
#define LAMBDA  0.95f
#define ETA     0.5f

#define NBLK 64
#define NTHR 512
#define KSPLIT_H 16
#define KSPLIT_O 8

// ---------------- device scratch ----------------
__device__ float g_h[BATCH * DH];
__device__ float g_parts[KSPLIT_H][BATCH * DH];
__device__ float g_zwg[T_STEPS * BATCH * DH];
__device__ float g_hist[T_STEPS - 1][BATCH * DH];
__device__ float g_gram[BATCH * 256];
__device__ float g_hsum[BATCH * 16];
__device__ float g_hp[KSPLIT_O][BATCH * DOUT];
__device__ float g_lossb[BATCH];
__device__ float g_accb[BATCH];

// pre-packed tf32 hi/lo B-fragments (frag-order) for the three weight matrices
__device__ float g_whf_hi[DH * DH];
__device__ float g_whf_lo[DH * DH];
__device__ float g_wgf_hi[DH * DG];
__device__ float g_wgf_lo[DH * DG];
__device__ float g_hwf_hi[DOUT * DH];
__device__ float g_hwf_lo[DOUT * DH];

// grid barrier
__device__ unsigned g_bar_cnt = 0;
__device__ volatile unsigned g_bar_gen = 0;

__device__ __forceinline__ void bar_sync(unsigned& gen) {
    __syncthreads();
    if (threadIdx.x == 0) {
        __threadfence();
        unsigned t = atomicAdd(&g_bar_cnt, 1u);
        if (t == NBLK - 1) {
            g_bar_cnt = 0u;
            __threadfence();
            g_bar_gen = gen + 1u;
        } else {
            while (g_bar_gen == gen) __nanosleep(32);
        }
    }
    __syncthreads();
    gen++;
}

// ---------------- tf32 helpers ----------------
__device__ __forceinline__ uint32_t f2tf32(float x) {
    uint32_t r;
    asm("cvt.rna.tf32.f32 %0, %1;" : "=r"(r) : "f"(x));
    return r;
}

__device__ __forceinline__ void mma8(float* c, uint4 a, uint32_t b0, uint32_t b1) {
    asm volatile(
        "mma.sync.aligned.m16n8k8.row.col.f32.tf32.tf32.f32 "
        "{%0,%1,%2,%3}, {%4,%5,%6,%7}, {%8,%9}, {%0,%1,%2,%3};"
        : "+f"(c[0]), "+f"(c[1]), "+f"(c[2]), "+f"(c[3])
        : "r"(a.x), "r"(a.y), "r"(a.z), "r"(a.w), "r"(b0), "r"(b1));
}

// ---------------- B-fragment prepack (one-time prolog) ----------------
// W row-major [N][K].  Frag addr for element (n,k):
//   n8=n>>3, k8=k>>3, lane=(n&7)*4+(k&3), reg=(k>>2)&1
//   addr = ((n8*(K/8) + k8)*32 + lane)*2 + reg
__device__ void pack_w(const float* __restrict__ W, float* __restrict__ hi,
                       float* __restrict__ lo, int NK, int klog, int kfrag8) {
    const int kmask = (1 << klog) - 1;
    for (int idx = blockIdx.x * NTHR + threadIdx.x; idx < NK; idx += NBLK * NTHR) {
        int n = idx >> klog, k = idx & kmask;
        float v = W[idx];
        uint32_t hb = f2tf32(v);
        uint32_t lb = f2tf32(v - __uint_as_float(hb));
        int n8 = n >> 3, k8 = k >> 3;
        int lane = (n & 7) * 4 + (k & 3);
        int reg = (k >> 2) & 1;
        size_t a = ((size_t)(n8 * kfrag8 + k8) * 32 + lane) * 2 + reg;
        hi[a] = __uint_as_float(hb);
        lo[a] = __uint_as_float(lb);
    }
}

// ---------------- A pack: X tile (64 rows x 64 k) -> smem frag order ----
// As layout: [k8 0..7][mtile 0..3][lane 0..31][reg 0..3]
__device__ __forceinline__ void a_pack(uint32_t* As_hi, uint32_t* As_lo,
                                       const float* __restrict__ X, int ldx, int k0) {
    const int t = threadIdx.x;
    const int row = t >> 3, cseg = t & 7;
    const float4* p = (const float4*)(X + (size_t)row * ldx + k0 + cseg * 8);
    float4 v0 = p[0], v1 = p[1];
    float xv[8] = {v0.x, v0.y, v0.z, v0.w, v1.x, v1.y, v1.z, v1.w};
    const int tr = row & 15, mt = row >> 4;
#pragma unroll
    for (int c = 0; c < 8; c++) {
        int reg = (tr >= 8 ? 1 : 0) + (c >= 4 ? 2 : 0);
        int lane = (tr & 7) * 4 + (c & 3);
        int idx = ((cseg * 4 + mt) * 32 + lane) * 4 + reg;
        uint32_t hb = f2tf32(xv[c]);
        uint32_t lb = f2tf32(xv[c] - __uint_as_float(hb));
        As_hi[idx] = hb;
        As_lo[idx] = lb;
    }
}

// ---------------- tf32x3 GEMM: out[m 0..63][n0..n0+255] over k --------
// 512 thr = 16 warps: warp (mw 0..3, nw 0..3) computes m16 x n64.
// X fp32 [64 x ldx]; W frags prepacked; out fp32 row-major ldo.
__device__ void gemm_tf32(uint32_t* As_hi, uint32_t* As_lo,
                          const float* __restrict__ X, int ldx,
                          const float* __restrict__ Whi,
                          const float* __restrict__ Wlo,
                          int kfrag8, int n0, int k0, int nch,
                          float* __restrict__ out, int ldo) {
    const int tid = threadIdx.x;
    const int warp = tid >> 5, lane = tid & 31;
    const int mw = warp >> 2, nw = warp & 3;

    float c[8][4];
#pragma unroll
    for (int i = 0; i < 8; i++)
#pragma unroll
        for (int j = 0; j < 4; j++) c[i][j] = 0.f;

    for (int ch = 0; ch < nch; ch++) {
        __syncthreads();
        a_pack(As_hi, As_lo, X, ldx, k0 + ch * 64);
        __syncthreads();
        const int k8base = (k0 + ch * 64) >> 3;
#pragma unroll 1
        for (int k8 = 0; k8 < 8; k8++) {
            const int ai = ((k8 * 4 + mw) * 32 + lane) * 4;
            uint4 ah = *(const uint4*)&As_hi[ai];
            uint4 al = *(const uint4*)&As_lo[ai];
            const int k8g = k8base + k8;
#pragma unroll
            for (int t8 = 0; t8 < 8; t8++) {
                const int n8g = (n0 + nw * 64 + t8 * 8) >> 3;
                const size_t ba = ((size_t)(n8g * kfrag8 + k8g) * 32 + lane) * 2;
                float2 bh = *(const float2*)&Whi[ba];
                float2 bl = *(const float2*)&Wlo[ba];
                uint32_t bh0 = __float_as_uint(bh.x), bh1 = __float_as_uint(bh.y);
                uint32_t bl0 = __float_as_uint(bl.x), bl1 = __float_as_uint(bl.y);
                mma8(c[t8], ah, bh0, bh1);   // hi*hi
                mma8(c[t8], ah, bl0, bl1);   // hi*lo
                mma8(c[t8], al, bh0, bh1);   // lo*hi
            }
        }
    }

    // epilogue: c0,c1 -> (row gid, cols 2tig,2tig+1); c2,c3 -> row gid+8
    const int gid = lane >> 2, tig = lane & 3;
#pragma unroll
    for (int t8 = 0; t8 < 8; t8++) {
        const int n = n0 + nw * 64 + t8 * 8 + tig * 2;
        const int m = mw * 16 + gid;
        *(float2*)&out[(size_t)m * ldo + n] = make_float2(c[t8][0], c[t8][1]);
        *(float2*)&out[(size_t)(m + 8) * ldo + n] = make_float2(c[t8][2], c[t8][3]);
    }
}

// ---------------- 512-thread multi-value block reduction ----------------
template <int NV>
__device__ __forceinline__ void reduce512(const float* v, float* bc, float (*red)[18]) {
    const int lane = threadIdx.x & 31, warp = threadIdx.x >> 5;
#pragma unroll
    for (int x = 0; x < NV; x++) {
        float s = v[x];
#pragma unroll
        for (int o = 16; o > 0; o >>= 1) s += __shfl_down_sync(0xffffffffu, s, o);
        if (lane == 0) red[warp][x] = s;
    }
    __syncthreads();
#pragma unroll
    for (int x = warp; x < NV; x += 16) {
        float s = (lane < 16) ? red[lane][x] : 0.f;
#pragma unroll
        for (int o = 8; o > 0; o >>= 1) s += __shfl_down_sync(0xffffffffu, s, o);
        if (lane == 0) bc[x] = s;
    }
    __syncthreads();
}

// ---------------- refine phase (block = batch element) ------------------
__device__ void refine_phase(int b, int t, bool last,
                             const float* __restrict__ b_h,
                             const float* __restrict__ gam,
                             const float* __restrict__ bet,
                             const float* __restrict__ alp) {
    const int tid = threadIdx.x, lane = tid & 31, warp = tid >> 5;
    const int i0 = tid, i1 = tid + 512;

    __shared__ float red[16][18];
    __shared__ float bcS[18];
    __shared__ float bc0[18];
    __shared__ float Gs[256];
    __shared__ float hsums[16];
    __shared__ float es[16];
    __shared__ float coef[4];

    const float g0 = gam[i0], g1 = gam[i1];
    const float be0 = bet[i0], be1 = bet[i1];

    float hb0 = b_h[i0] + __ldcg(&g_zwg[((size_t)t * BATCH + b) * DH + i0]);
    float hb1 = b_h[i1] + __ldcg(&g_zwg[((size_t)t * BATCH + b) * DH + i1]);
    if (t > 0) {
#pragma unroll
        for (int s = 0; s < KSPLIT_H; s++) {
            hb0 += __ldcg(&g_parts[s][b * DH + i0]);
            hb1 += __ldcg(&g_parts[s][b * DH + i1]);
        }
    }

    float hv0[15], hv1[15];
#pragma unroll
    for (int tau = 0; tau < 15; tau++) {
        hv0[tau] = g_hist[tau][b * DH + i0];
        hv1[tau] = g_hist[tau][b * DH + i1];
    }

    if (tid < 256) Gs[tid] = g_gram[b * 256 + tid];
    if (tid < 16)  hsums[tid] = g_hsum[b * 16 + tid];

    {
        float p[17];
#pragma unroll
        for (int tau = 0; tau < 15; tau++)
            p[tau] = hv0[tau] * hb0 + hv1[tau] * hb1;
        p[15] = hb0 + hb1;
        p[16] = hb0 * hb0 + hb1 * hb1;
        reduce512<17>(p, bc0, red);
    }

    float mu = bc0[15] * (1.f / DH);
    float var = bc0[16] * (1.f / DH) - mu * mu;
    float rstd = rsqrtf(var + 1e-5f);
    float h0 = fmaxf((hb0 - mu) * rstd * g0 + be0, 0.f);
    float h1 = fmaxf((hb1 - mu) * rstd * g1 + be1, 0.f);

    const float alpha = *alp;
    float wdl = 0.f;
    if (warp == 0 && lane < t)
        wdl = ETA * powf(LAMBDA, (float)(t - 1 - lane));

#pragma unroll
    for (int s = 0; s < S_STEPS; s++) {
        {
            float qv[16];
#pragma unroll
            for (int tau = 0; tau < 15; tau++)
                qv[tau] = hv0[tau] * h0 + hv1[tau] * h1;
            qv[15] = h0 * h0 + h1 * h1;
            reduce512<16>(qv, bcS, red);
        }

        if (warp == 0) {
            float d = (lane < 16) ? bcS[lane] : 0.f;
            float e = wdl * d;
            if (lane < 16) es[lane] = e;
            __syncwarp();
            float f = 0.f;
            if (lane < 16) {
#pragma unroll
                for (int sg = 0; sg < 15; sg++)
                    f += es[sg] * Gs[lane * 16 + sg];
            }
            float hbd = (lane < 16) ? bc0[lane] : 0.f;
            float hsm = (lane < 16) ? hsums[lane] : 0.f;
            float pA = e * d;
            float pB = e * hbd;
            float pC = e * hsm;
            float pD = e * f;
#pragma unroll
            for (int o = 8; o > 0; o >>= 1) {
                pA += __shfl_down_sync(0xffffffffu, pA, o);
                pB += __shfl_down_sync(0xffffffffu, pB, o);
                pC += __shfl_down_sync(0xffffffffu, pC, o);
                pD += __shfl_down_sync(0xffffffffu, pD, o);
            }
            if (lane == 0) {
                float c1, c2;
                if (!last) {
                    float hh = bcS[15];
                    float n1 = sqrtf(hh) + 1e-6f;
                    float n2 = sqrtf(fmaxf(pD, 0.f)) + 1e-6f;
                    float R  = pA / (n1 * n2 + 1e-6f);
                    float Rp = fminf(fmaxf(R, 0.f), 1.f);
                    float spp = fmaxf(alpha, 0.f) + log1pf(expf(-fabsf(alpha)));
                    float spn = fmaxf(-alpha, 0.f) + log1pf(expf(-fabsf(alpha)));
                    float kco = (alpha >= 0.f) ? (1.f + spp) : (1.f / (1.f + spn));
                    float a   = 1.f - powf(1.f - Rp, kco);
                    c1 = 1.f - a * a;
                    c2 = a;
                } else {
                    c1 = 1.f;
                    c2 = 1.f;
                }
                float sum_hn  = c1 * bc0[15] + c2 * pC;
                float sum_hn2 = c1 * c1 * bc0[16] + 2.f * c1 * c2 * pB +
                                c2 * c2 * pD;
                float mu_n  = sum_hn * (1.f / DH);
                float var_n = sum_hn2 * (1.f / DH) - mu_n * mu_n;
                coef[0] = c1;
                coef[1] = c2;
                coef[2] = mu_n;
                coef[3] = rsqrtf(var_n + 1e-5f);
            }
        }
        __syncthreads();

        float Ah0 = 0.f, Ah1 = 0.f;
#pragma unroll
        for (int tau = 0; tau < 15; tau++) {
            Ah0 += es[tau] * hv0[tau];
            Ah1 += es[tau] * hv1[tau];
        }
        const float c1 = coef[0], c2 = coef[1], mun = coef[2], rsn = coef[3];
        float hn0 = c1 * hb0 + c2 * Ah0;
        float hn1 = c1 * hb1 + c2 * Ah1;
        h0 = fmaxf((hn0 - mun) * rsn * g0 + be0, 0.f);
        h1 = fmaxf((hn1 - mun) * rsn * g1 + be1, 0.f);
        __syncthreads();
    }

    g_h[b * DH + i0] = h0;
    g_h[b * DH + i1] = h1;

    if (!last) {
        float r[17];
#pragma unroll
        for (int tau = 0; tau < 15; tau++)
            r[tau] = hv0[tau] * h0 + hv1[tau] * h1;
        r[15] = h0 + h1;
        r[16] = h0 * h0 + h1 * h1;
        reduce512<17>(r, bcS, red);
        if (tid < t) {
            g_gram[b * 256 + t * 16 + tid] = bcS[tid];
            g_gram[b * 256 + tid * 16 + t] = bcS[tid];
        }
        if (tid == 0) {
            g_gram[b * 256 + t * 16 + t] = bcS[16];
            g_hsum[b * 16 + t] = bcS[15];
        }
        g_hist[t][b * DH + i0] = h0;
        g_hist[t][b * DH + i1] = h1;
    }
}

// ---------------- loss phase ----------------
__device__ void loss_phase(int b, const float* __restrict__ clean,
                           const float* __restrict__ head_b) {
    const int o = threadIdx.x;
    __shared__ float red[16][18];
    __shared__ float bc[18];
    float pred = head_b[o];
#pragma unroll
    for (int s = 0; s < KSPLIT_O; s++) pred += __ldcg(&g_hp[s][b * DOUT + o]);
    float c = clean[b * DOUT + o];
    float d = pred - c;
    float v[4] = {pred * c, pred * pred, c * c, d * d};
    reduce512<4>(v, bc, red);
    if (o == 0) {
        g_lossb[b] = bc[3] / (bc[2] + 1e-6f);
        g_accb[b]  = bc[0] / ((sqrtf(bc[1]) + 1e-6f) * (sqrtf(bc[2]) + 1e-6f));
    }
}

// ---------------- the one persistent kernel ----------------
__global__ void __launch_bounds__(NTHR, 1) fused_kernel(
    const float* __restrict__ z_seq, const float* __restrict__ clean,
    const float* __restrict__ W_h, const float* __restrict__ W_g,
    const float* __restrict__ b_h, const float* __restrict__ ln_g,
    const float* __restrict__ ln_b, const float* __restrict__ alpha,
    const float* __restrict__ head_W, const float* __restrict__ head_b,
    float* __restrict__ out) {
    __shared__ __align__(16) uint32_t As_hi[8 * 4 * 32 * 4];   // 16 KB
    __shared__ __align__(16) uint32_t As_lo[8 * 4 * 32 * 4];   // 16 KB

    unsigned gen = g_bar_gen;
    const int bi = blockIdx.x;

    // phase 0: prepack all weight matrices into tf32 hi/lo fragments
    pack_w(W_g,    g_wgf_hi, g_wgf_lo, DH * DG,  9, DG / 8);
    pack_w(W_h,    g_whf_hi, g_whf_lo, DH * DH, 10, DH / 8);
    pack_w(head_W, g_hwf_hi, g_hwf_lo, DOUT * DH, 10, DH / 8);
    bar_sync(gen);

    // phase 1: zwg = z @ W_g^T  (1024 x 1024 x 512), 16 m-tiles x 4 n-tiles
    {
        const int mt = bi >> 2, nt = bi & 3;
        gemm_tf32(As_hi, As_lo,
                  z_seq + (size_t)mt * 64 * DG, DG,
                  g_wgf_hi, g_wgf_lo, DG / 8,
                  nt * 256, 0, 8,
                  g_zwg + (size_t)mt * 64 * DH, DH);
    }
    bar_sync(gen);

    for (int t = 0; t < T_STEPS; t++) {
        if (t > 0) {
            // wh: 4 n-tiles x 16 k-splits (k=64) = 64 blocks
            const int nt = bi & 3, ks = bi >> 2;
            gemm_tf32(As_hi, As_lo, g_h, DH,
                      g_whf_hi, g_whf_lo, DH / 8,
                      nt * 256, ks * 64, 1,
                      g_parts[ks], DH);
            bar_sync(gen);
        }
        refine_phase(bi, t, t == T_STEPS - 1, b_h, ln_g, ln_b, alpha);
        bar_sync(gen);
    }

    // head GEMM: 2 n-tiles x 8 k-splits (k=128) = 16 blocks
    if (bi < 16) {
        const int nt = bi & 1, ks = bi >> 1;
        gemm_tf32(As_hi, As_lo, g_h, DH,
                  g_hwf_hi, g_hwf_lo, DH / 8,
                  nt * 256, ks * 128, 2,
                  g_hp[ks], DOUT);
    }
    bar_sync(gen);

    loss_phase(bi, clean, head_b);
    bar_sync(gen);

    if (bi == 0 && threadIdx.x < 32) {
        const int lane = threadIdx.x;
        float l = g_lossb[lane] + g_lossb[lane + 32];
        float a = g_accb[lane] + g_accb[lane + 32];
#pragma unroll
        for (int o = 16; o > 0; o >>= 1) {
            l += __shfl_down_sync(0xffffffffu, l, o);
            a += __shfl_down_sync(0xffffffffu, a, o);
        }
        if (lane == 0) {
            out[0] = l * (1.f / BATCH);
            out[1] = a * (1.f / BATCH);
        }
    }
}

// ---------------- launch ----------------
extern "C" void kernel_launch(void* const* d_in, const int* in_sizes, int n_in,
                              void* d_out, int out_size) {
    const float* z_seq  = (const float*)d_in[0];
    const float* clean  = (const float*)d_in[1];
    const float* W_h    = (const float*)d_in[2];
    const float* W_g    = (const float*)d_in[3];
    const float* b_h    = (const float*)d_in[4];
    const float* ln_g   = (const float*)d_in[5];
    const float* ln_b   = (const float*)d_in[6];
    const float* alpha  = (const float*)d_in[7];
    const float* head_W = (const float*)d_in[8];
    const float* head_b = (const float*)d_in[9];
    float* out = (float*)d_out;

    fused_kernel<<<NBLK, NTHR>>>(z_seq, clean, W_h, W_g, b_h, ln_g, ln_b,
                                 alpha, head_W, head_b, out);
}

// round 10
// speedup vs baseline: 1.0072x; 1.0028x over previous
#include <cuda_runtime.h>
#include <math.h>
#include <stdint.h>

#define T_STEPS 16
#define BATCH   64
#define DG      512
#define DH      1024
#define DOUT    512
#define S_STEPS 3
#define LAMBDA  0.95f
#define ETA     0.5f

#define NBLK 64
#define NTHR 512
#define KSPLIT_H 16
#define KSPLIT_O 8

// ---------------- device scratch ----------------
__device__ float g_h[BATCH * DH];
__device__ float g_parts[KSPLIT_H][BATCH * DH];
__device__ float g_zwg[T_STEPS * BATCH * DH];
__device__ float g_hist[T_STEPS - 1][BATCH * DH];
__device__ float g_gram[BATCH * 256];
__device__ float g_hsum[BATCH * 16];
__device__ float g_hp[KSPLIT_O][BATCH * DOUT];
__device__ float g_lossb[BATCH];
__device__ float g_accb[BATCH];

// pre-packed tf32 hi/lo B-fragments (frag-order) for the three weight matrices
__device__ float g_whf_hi[DH * DH];
__device__ float g_whf_lo[DH * DH];
__device__ float g_wgf_hi[DH * DG];
__device__ float g_wgf_lo[DH * DG];
__device__ float g_hwf_hi[DOUT * DH];
__device__ float g_hwf_lo[DOUT * DH];

// grid barrier
__device__ unsigned g_bar_cnt = 0;
__device__ volatile unsigned g_bar_gen = 0;

__device__ __forceinline__ void bar_sync(unsigned& gen) {
    __syncthreads();
    if (threadIdx.x == 0) {
        __threadfence();
        unsigned t = atomicAdd(&g_bar_cnt, 1u);
        if (t == NBLK - 1) {
            g_bar_cnt = 0u;
            __threadfence();
            g_bar_gen = gen + 1u;
        } else {
            while (g_bar_gen == gen) __nanosleep(32);
        }
    }
    __syncthreads();
    gen++;
}

// ---------------- tf32 helpers ----------------
__device__ __forceinline__ uint32_t f2tf32(float x) {
    uint32_t r;
    asm("cvt.rna.tf32.f32 %0, %1;" : "=r"(r) : "f"(x));
    return r;
}

__device__ __forceinline__ void mma8(float* c, uint4 a, uint32_t b0, uint32_t b1) {
    asm volatile(
        "mma.sync.aligned.m16n8k8.row.col.f32.tf32.tf32.f32 "
        "{%0,%1,%2,%3}, {%4,%5,%6,%7}, {%8,%9}, {%0,%1,%2,%3};"
        : "+f"(c[0]), "+f"(c[1]), "+f"(c[2]), "+f"(c[3])
        : "r"(a.x), "r"(a.y), "r"(a.z), "r"(a.w), "r"(b0), "r"(b1));
}

// ---------------- B-fragment prepack (one-time prolog) ----------------
// W row-major [N][K].  Frag addr for element (n,k):
//   n8=n>>3, k8=k>>3, lane=(n&7)*4+(k&3), reg=(k>>2)&1
//   addr = ((n8*(K/8) + k8)*32 + lane)*2 + reg
__device__ void pack_w(const float* __restrict__ W, float* __restrict__ hi,
                       float* __restrict__ lo, int NK, int klog, int kfrag8) {
    const int kmask = (1 << klog) - 1;
    for (int idx = blockIdx.x * NTHR + threadIdx.x; idx < NK; idx += NBLK * NTHR) {
        int n = idx >> klog, k = idx & kmask;
        float v = W[idx];
        uint32_t hb = f2tf32(v);
        uint32_t lb = f2tf32(v - __uint_as_float(hb));
        int n8 = n >> 3, k8 = k >> 3;
        int lane = (n & 7) * 4 + (k & 3);
        int reg = (k >> 2) & 1;
        size_t a = ((size_t)(n8 * kfrag8 + k8) * 32 + lane) * 2 + reg;
        hi[a] = __uint_as_float(hb);
        lo[a] = __uint_as_float(lb);
    }
}

// ---------------- A pack: X tile (64 rows x 64 k) -> smem frag order ----
// As layout: [k8 0..7][mtile 0..3][lane 0..31][reg 0..3]
__device__ __forceinline__ void a_pack(uint32_t* As_hi, uint32_t* As_lo,
                                       const float* __restrict__ X, int ldx, int k0) {
    const int t = threadIdx.x;
    const int row = t >> 3, cseg = t & 7;
    const float4* p = (const float4*)(X + (size_t)row * ldx + k0 + cseg * 8);
    float4 v0 = p[0], v1 = p[1];
    float xv[8] = {v0.x, v0.y, v0.z, v0.w, v1.x, v1.y, v1.z, v1.w};
    const int tr = row & 15, mt = row >> 4;
#pragma unroll
    for (int c = 0; c < 8; c++) {
        int reg = (tr >= 8 ? 1 : 0) + (c >= 4 ? 2 : 0);
        int lane = (tr & 7) * 4 + (c & 3);
        int idx = ((cseg * 4 + mt) * 32 + lane) * 4 + reg;
        uint32_t hb = f2tf32(xv[c]);
        uint32_t lb = f2tf32(xv[c] - __uint_as_float(hb));
        As_hi[idx] = hb;
        As_lo[idx] = lb;
    }
}

// ---------------- tf32x3 GEMM: out[m 0..63][n0..n0+255] over k --------
// 512 thr = 16 warps: warp (mw 0..3, nw 0..3) computes m16 x n64.
// X fp32 [64 x ldx]; W frags prepacked; out fp32 row-major ldo.
__device__ void gemm_tf32(uint32_t* As_hi, uint32_t* As_lo,
                          const float* __restrict__ X, int ldx,
                          const float* __restrict__ Whi,
                          const float* __restrict__ Wlo,
                          int kfrag8, int n0, int k0, int nch,
                          float* __restrict__ out, int ldo) {
    const int tid = threadIdx.x;
    const int warp = tid >> 5, lane = tid & 31;
    const int mw = warp >> 2, nw = warp & 3;

    float c[8][4];
#pragma unroll
    for (int i = 0; i < 8; i++)
#pragma unroll
        for (int j = 0; j < 4; j++) c[i][j] = 0.f;

    for (int ch = 0; ch < nch; ch++) {
        __syncthreads();
        a_pack(As_hi, As_lo, X, ldx, k0 + ch * 64);
        __syncthreads();
        const int k8base = (k0 + ch * 64) >> 3;
#pragma unroll 1
        for (int k8 = 0; k8 < 8; k8++) {
            const int ai = ((k8 * 4 + mw) * 32 + lane) * 4;
            uint4 ah = *(const uint4*)&As_hi[ai];
            uint4 al = *(const uint4*)&As_lo[ai];
            const int k8g = k8base + k8;
#pragma unroll
            for (int t8 = 0; t8 < 8; t8++) {
                const int n8g = (n0 + nw * 64 + t8 * 8) >> 3;
                const size_t ba = ((size_t)(n8g * kfrag8 + k8g) * 32 + lane) * 2;
                float2 bh = *(const float2*)&Whi[ba];
                float2 bl = *(const float2*)&Wlo[ba];
                uint32_t bh0 = __float_as_uint(bh.x), bh1 = __float_as_uint(bh.y);
                uint32_t bl0 = __float_as_uint(bl.x), bl1 = __float_as_uint(bl.y);
                mma8(c[t8], ah, bh0, bh1);   // hi*hi
                mma8(c[t8], ah, bl0, bl1);   // hi*lo
                mma8(c[t8], al, bh0, bh1);   // lo*hi
            }
        }
    }

    // epilogue: c0,c1 -> (row gid, cols 2tig,2tig+1); c2,c3 -> row gid+8
    const int gid = lane >> 2, tig = lane & 3;
#pragma unroll
    for (int t8 = 0; t8 < 8; t8++) {
        const int n = n0 + nw * 64 + t8 * 8 + tig * 2;
        const int m = mw * 16 + gid;
        *(float2*)&out[(size_t)m * ldo + n] = make_float2(c[t8][0], c[t8][1]);
        *(float2*)&out[(size_t)(m + 8) * ldo + n] = make_float2(c[t8][2], c[t8][3]);
    }
}

// ---------------- 512-thread multi-value block reduction ----------------
template <int NV>
__device__ __forceinline__ void reduce512(const float* v, float* bc, float (*red)[18]) {
    const int lane = threadIdx.x & 31, warp = threadIdx.x >> 5;
#pragma unroll
    for (int x = 0; x < NV; x++) {
        float s = v[x];
#pragma unroll
        for (int o = 16; o > 0; o >>= 1) s += __shfl_down_sync(0xffffffffu, s, o);
        if (lane == 0) red[warp][x] = s;
    }
    __syncthreads();
#pragma unroll
    for (int x = warp; x < NV; x += 16) {
        float s = (lane < 16) ? red[lane][x] : 0.f;
#pragma unroll
        for (int o = 8; o > 0; o >>= 1) s += __shfl_down_sync(0xffffffffu, s, o);
        if (lane == 0) bc[x] = s;
    }
    __syncthreads();
}

// ---------------- refine phase (block = batch element) ------------------
__device__ void refine_phase(int b, int t, bool last,
                             const float* __restrict__ b_h,
                             const float* __restrict__ gam,
                             const float* __restrict__ bet,
                             const float* __restrict__ alp) {
    const int tid = threadIdx.x, lane = tid & 31, warp = tid >> 5;
    const int i0 = tid, i1 = tid + 512;

    __shared__ float red[16][18];
    __shared__ float bcS[18];
    __shared__ float bc0[18];
    __shared__ float Gs[256];
    __shared__ float hsums[16];
    __shared__ float es[16];
    __shared__ float coef[4];

    const float g0 = gam[i0], g1 = gam[i1];
    const float be0 = bet[i0], be1 = bet[i1];

    float hb0 = b_h[i0] + __ldcg(&g_zwg[((size_t)t * BATCH + b) * DH + i0]);
    float hb1 = b_h[i1] + __ldcg(&g_zwg[((size_t)t * BATCH + b) * DH + i1]);
    if (t > 0) {
#pragma unroll
        for (int s = 0; s < KSPLIT_H; s++) {
            hb0 += __ldcg(&g_parts[s][b * DH + i0]);
            hb1 += __ldcg(&g_parts[s][b * DH + i1]);
        }
    }

    float hv0[15], hv1[15];
#pragma unroll
    for (int tau = 0; tau < 15; tau++) {
        hv0[tau] = g_hist[tau][b * DH + i0];
        hv1[tau] = g_hist[tau][b * DH + i1];
    }

    if (tid < 256) Gs[tid] = g_gram[b * 256 + tid];
    if (tid < 16)  hsums[tid] = g_hsum[b * 16 + tid];

    {
        float p[17];
#pragma unroll
        for (int tau = 0; tau < 15; tau++)
            p[tau] = hv0[tau] * hb0 + hv1[tau] * hb1;
        p[15] = hb0 + hb1;
        p[16] = hb0 * hb0 + hb1 * hb1;
        reduce512<17>(p, bc0, red);
    }

    float mu = bc0[15] * (1.f / DH);
    float var = bc0[16] * (1.f / DH) - mu * mu;
    float rstd = rsqrtf(var + 1e-5f);
    float h0 = fmaxf((hb0 - mu) * rstd * g0 + be0, 0.f);
    float h1 = fmaxf((hb1 - mu) * rstd * g1 + be1, 0.f);

    const float alpha = *alp;
    float wdl = 0.f;
    if (warp == 0 && lane < t)
        wdl = ETA * powf(LAMBDA, (float)(t - 1 - lane));

#pragma unroll
    for (int s = 0; s < S_STEPS; s++) {
        {
            float qv[16];
#pragma unroll
            for (int tau = 0; tau < 15; tau++)
                qv[tau] = hv0[tau] * h0 + hv1[tau] * h1;
            qv[15] = h0 * h0 + h1 * h1;
            reduce512<16>(qv, bcS, red);
        }

        if (warp == 0) {
            float d = (lane < 16) ? bcS[lane] : 0.f;
            float e = wdl * d;
            if (lane < 16) es[lane] = e;
            __syncwarp();
            float f = 0.f;
            if (lane < 16) {
#pragma unroll
                for (int sg = 0; sg < 15; sg++)
                    f += es[sg] * Gs[lane * 16 + sg];
            }
            float hbd = (lane < 16) ? bc0[lane] : 0.f;
            float hsm = (lane < 16) ? hsums[lane] : 0.f;
            float pA = e * d;
            float pB = e * hbd;
            float pC = e * hsm;
            float pD = e * f;
#pragma unroll
            for (int o = 8; o > 0; o >>= 1) {
                pA += __shfl_down_sync(0xffffffffu, pA, o);
                pB += __shfl_down_sync(0xffffffffu, pB, o);
                pC += __shfl_down_sync(0xffffffffu, pC, o);
                pD += __shfl_down_sync(0xffffffffu, pD, o);
            }
            if (lane == 0) {
                float c1, c2;
                if (!last) {
                    float hh = bcS[15];
                    float n1 = sqrtf(hh) + 1e-6f;
                    float n2 = sqrtf(fmaxf(pD, 0.f)) + 1e-6f;
                    float R  = pA / (n1 * n2 + 1e-6f);
                    float Rp = fminf(fmaxf(R, 0.f), 1.f);
                    float spp = fmaxf(alpha, 0.f) + log1pf(expf(-fabsf(alpha)));
                    float spn = fmaxf(-alpha, 0.f) + log1pf(expf(-fabsf(alpha)));
                    float kco = (alpha >= 0.f) ? (1.f + spp) : (1.f / (1.f + spn));
                    float a   = 1.f - powf(1.f - Rp, kco);
                    c1 = 1.f - a * a;
                    c2 = a;
                } else {
                    c1 = 1.f;
                    c2 = 1.f;
                }
                float sum_hn  = c1 * bc0[15] + c2 * pC;
                float sum_hn2 = c1 * c1 * bc0[16] + 2.f * c1 * c2 * pB +
                                c2 * c2 * pD;
                float mu_n  = sum_hn * (1.f / DH);
                float var_n = sum_hn2 * (1.f / DH) - mu_n * mu_n;
                coef[0] = c1;
                coef[1] = c2;
                coef[2] = mu_n;
                coef[3] = rsqrtf(var_n + 1e-5f);
            }
        }
        __syncthreads();

        float Ah0 = 0.f, Ah1 = 0.f;
#pragma unroll
        for (int tau = 0; tau < 15; tau++) {
            Ah0 += es[tau] * hv0[tau];
            Ah1 += es[tau] * hv1[tau];
        }
        const float c1 = coef[0], c2 = coef[1], mun = coef[2], rsn = coef[3];
        float hn0 = c1 * hb0 + c2 * Ah0;
        float hn1 = c1 * hb1 + c2 * Ah1;
        h0 = fmaxf((hn0 - mun) * rsn * g0 + be0, 0.f);
        h1 = fmaxf((hn1 - mun) * rsn * g1 + be1, 0.f);
        __syncthreads();
    }

    g_h[b * DH + i0] = h0;
    g_h[b * DH + i1] = h1;

    if (!last) {
        float r[17];
#pragma unroll
        for (int tau = 0; tau < 15; tau++)
            r[tau] = hv0[tau] * h0 + hv1[tau] * h1;
        r[15] = h0 + h1;
        r[16] = h0 * h0 + h1 * h1;
        reduce512<17>(r, bcS, red);
        if (tid < t) {
            g_gram[b * 256 + t * 16 + tid] = bcS[tid];
            g_gram[b * 256 + tid * 16 + t] = bcS[tid];
        }
        if (tid == 0) {
            g_gram[b * 256 + t * 16 + t] = bcS[16];
            g_hsum[b * 16 + t] = bcS[15];
        }
        g_hist[t][b * DH + i0] = h0;
        g_hist[t][b * DH + i1] = h1;
    }
}

// ---------------- loss phase ----------------
__device__ void loss_phase(int b, const float* __restrict__ clean,
                           const float* __restrict__ head_b) {
    const int o = threadIdx.x;
    __shared__ float red[16][18];
    __shared__ float bc[18];
    float pred = head_b[o];
#pragma unroll
    for (int s = 0; s < KSPLIT_O; s++) pred += __ldcg(&g_hp[s][b * DOUT + o]);
    float c = clean[b * DOUT + o];
    float d = pred - c;
    float v[4] = {pred * c, pred * pred, c * c, d * d};
    reduce512<4>(v, bc, red);
    if (o == 0) {
        g_lossb[b] = bc[3] / (bc[2] + 1e-6f);
        g_accb[b]  = bc[0] / ((sqrtf(bc[1]) + 1e-6f) * (sqrtf(bc[2]) + 1e-6f));
    }
}

// ---------------- the one persistent kernel ----------------
__global__ void __launch_bounds__(NTHR, 1) fused_kernel(
    const float* __restrict__ z_seq, const float* __restrict__ clean,
    const float* __restrict__ W_h, const float* __restrict__ W_g,
    const float* __restrict__ b_h, const float* __restrict__ ln_g,
    const float* __restrict__ ln_b, const float* __restrict__ alpha,
    const float* __restrict__ head_W, const float* __restrict__ head_b,
    float* __restrict__ out) {
    __shared__ __align__(16) uint32_t As_hi[8 * 4 * 32 * 4];   // 16 KB
    __shared__ __align__(16) uint32_t As_lo[8 * 4 * 32 * 4];   // 16 KB

    unsigned gen = g_bar_gen;
    const int bi = blockIdx.x;

    // phase 0: prepack all weight matrices into tf32 hi/lo fragments
    pack_w(W_g,    g_wgf_hi, g_wgf_lo, DH * DG,  9, DG / 8);
    pack_w(W_h,    g_whf_hi, g_whf_lo, DH * DH, 10, DH / 8);
    pack_w(head_W, g_hwf_hi, g_hwf_lo, DOUT * DH, 10, DH / 8);
    bar_sync(gen);

    // phase 1: zwg = z @ W_g^T  (1024 x 1024 x 512), 16 m-tiles x 4 n-tiles
    {
        const int mt = bi >> 2, nt = bi & 3;
        gemm_tf32(As_hi, As_lo,
                  z_seq + (size_t)mt * 64 * DG, DG,
                  g_wgf_hi, g_wgf_lo, DG / 8,
                  nt * 256, 0, 8,
                  g_zwg + (size_t)mt * 64 * DH, DH);
    }
    bar_sync(gen);

    for (int t = 0; t < T_STEPS; t++) {
        if (t > 0) {
            // wh: 4 n-tiles x 16 k-splits (k=64) = 64 blocks
            const int nt = bi & 3, ks = bi >> 2;
            gemm_tf32(As_hi, As_lo, g_h, DH,
                      g_whf_hi, g_whf_lo, DH / 8,
                      nt * 256, ks * 64, 1,
                      g_parts[ks], DH);
            bar_sync(gen);
        }
        refine_phase(bi, t, t == T_STEPS - 1, b_h, ln_g, ln_b, alpha);
        bar_sync(gen);
    }

    // head GEMM: 2 n-tiles x 8 k-splits (k=128) = 16 blocks
    if (bi < 16) {
        const int nt = bi & 1, ks = bi >> 1;
        gemm_tf32(As_hi, As_lo, g_h, DH,
                  g_hwf_hi, g_hwf_lo, DH / 8,
                  nt * 256, ks * 128, 2,
                  g_hp[ks], DOUT);
    }
    bar_sync(gen);

    loss_phase(bi, clean, head_b);
    bar_sync(gen);

    if (bi == 0 && threadIdx.x < 32) {
        const int lane = threadIdx.x;
        float l = g_lossb[lane] + g_lossb[lane + 32];
        float a = g_accb[lane] + g_accb[lane + 32];
#pragma unroll
        for (int o = 16; o > 0; o >>= 1) {
            l += __shfl_down_sync(0xffffffffu, l, o);
            a += __shfl_down_sync(0xffffffffu, a, o);
        }
        if (lane == 0) {
            out[0] = l * (1.f / BATCH);
            out[1] = a * (1.f / BATCH);
        }
    }
}

// ---------------- launch ----------------
extern "C" void kernel_launch(void* const* d_in, const int* in_sizes, int n_in,
                              void* d_out, int out_size) {
    const float* z_seq  = (const float*)d_in[0];
    const float* clean  = (const float*)d_in[1];
    const float* W_h    = (const float*)d_in[2];
    const float* W_g    = (const float*)d_in[3];
    const float* b_h    = (const float*)d_in[4];
    const float* ln_g   = (const float*)d_in[5];
    const float* ln_b   = (const float*)d_in[6];
    const float* alpha  = (const float*)d_in[7];
    const float* head_W = (const float*)d_in[8];
    const float* head_b = (const float*)d_in[9];
    float* out = (float*)d_out;

    fused_kernel<<<NBLK, NTHR>>>(z_seq, clean, W_h, W_g, b_h, ln_g, ln_b,
                                 alpha, head_W, head_b, out);
}